// round 8
// baseline (speedup 1.0000x reference)
#include <cuda_runtime.h>
#include <cuda_fp16.h>
#include <cstdint>

#define NB      1024
#define NN      256
#define ITERS   100
#define EPSD    1e-8f
#define THREADS 512

// padded K layout: 256 rows x 264 halves (528 B row stride)
#define ROWB    528

// smem byte offsets
#define OFF_KS   0                 // 256*264*2 = 135168
#define OFF_UH   135168            // 256 half
#define OFF_VH   135680            // 256 half
#define OFF_US   136192            // 256 f32
#define OFF_VS   137216
#define OFF_AS   138240
#define OFF_BS   139264
#define OFF_RED  140288            // 16 f32
#define SMEM_BYTES 140352

__device__ float g_batch_cost[NB];

__device__ __forceinline__ uint32_t smem_u32(const void* p) {
    uint32_t r;
    asm("{ .reg .u64 t; cvta.to.shared.u64 t, %1; cvt.u32.u64 %0, t; }" : "=r"(r) : "l"(p));
    return r;
}

__device__ __forceinline__ void ldsm_x4(uint32_t& r0, uint32_t& r1, uint32_t& r2,
                                        uint32_t& r3, uint32_t addr) {
    asm volatile("ldmatrix.sync.aligned.m8n8.x4.shared.b16 {%0,%1,%2,%3}, [%4];"
                 : "=r"(r0), "=r"(r1), "=r"(r2), "=r"(r3) : "r"(addr));
}

__device__ __forceinline__ void ldsm_x4_trans(uint32_t& r0, uint32_t& r1, uint32_t& r2,
                                              uint32_t& r3, uint32_t addr) {
    asm volatile("ldmatrix.sync.aligned.m8n8.x4.trans.shared.b16 {%0,%1,%2,%3}, [%4];"
                 : "=r"(r0), "=r"(r1), "=r"(r2), "=r"(r3) : "r"(addr));
}

__device__ __forceinline__ void mma16816(float c[4], uint32_t a0, uint32_t a1,
                                         uint32_t a2, uint32_t a3,
                                         uint32_t b0, uint32_t b1) {
    asm volatile(
        "mma.sync.aligned.m16n8k16.row.col.f32.f16.f16.f32 "
        "{%0,%1,%2,%3}, {%4,%5,%6,%7}, {%8,%9}, {%0,%1,%2,%3};"
        : "+f"(c[0]), "+f"(c[1]), "+f"(c[2]), "+f"(c[3])
        : "r"(a0), "r"(a1), "r"(a2), "r"(a3), "r"(b0), "r"(b1));
}

// exp(-10*c) = 2^(-10*log2e*c), deg-5 poly, rel err ~2.4e-6
__device__ __forceinline__ float fast_exp_n10(float c) {
    float t = c * (-14.426950408889634f);
    float r = rintf(t);
    float f = t - r;
    float p = 1.3333558146e-3f;
    p = fmaf(p, f, 9.6181291076e-3f);
    p = fmaf(p, f, 5.5504108664e-2f);
    p = fmaf(p, f, 2.4022650696e-1f);
    p = fmaf(p, f, 6.9314718056e-1f);
    p = fmaf(p, f, 1.0f);
    return __int_as_float(__float_as_int(p) + (((int)r) << 23));
}

__device__ __forceinline__ float block_reduce(float val, float* red, int t) {
    #pragma unroll
    for (int o = 16; o > 0; o >>= 1)
        val += __shfl_xor_sync(0xffffffffu, val, o);
    if ((t & 31) == 0) red[t >> 5] = val;
    __syncthreads();
    if (t < 32) {
        float v2 = (t < (THREADS / 32)) ? red[t] : 0.0f;
        #pragma unroll
        for (int o = 8; o > 0; o >>= 1)
            v2 += __shfl_xor_sync(0xffffffffu, v2, o);
        if (t == 0) red[0] = v2;
    }
    __syncthreads();
    float out = red[0];
    __syncthreads();
    return out;
}

__global__ void __launch_bounds__(THREADS, 1)
sinkhorn_main(const float* __restrict__ Cmat,
              const float* __restrict__ mp,
              const float* __restrict__ mt) {
    extern __shared__ __align__(16) char A0[];
    __half* uh  = (__half*)(A0 + OFF_UH);
    __half* vh  = (__half*)(A0 + OFF_VH);
    float*  u_s = (float*)(A0 + OFF_US);
    float*  v_s = (float*)(A0 + OFF_VS);
    float*  a_s = (float*)(A0 + OFF_AS);
    float*  b_s = (float*)(A0 + OFF_BS);
    float*  red = (float*)(A0 + OFF_RED);

    const int t    = threadIdx.x;
    const int lane = t & 31;
    const int w    = t >> 5;              // warp 0..15
    const int b    = blockIdx.x;
    const float* Cb = Cmat + (size_t)b * (NN * NN);
    const uint32_t ks_base = smem_u32(A0 + OFF_KS);

    // ---- build K = exp(-C/eps) fp16 into padded row-major smem ----
    {
        const float4* C4 = (const float4*)Cb;
        for (int i = t; i < (NN * NN / 4); i += THREADS) {
            float4 c4 = C4[i];
            int n = i >> 6;
            int m = (i & 63) << 2;
            __half2 h0 = __floats2half2_rn(fast_exp_n10(c4.x), fast_exp_n10(c4.y));
            __half2 h1 = __floats2half2_rn(fast_exp_n10(c4.z), fast_exp_n10(c4.w));
            uint2 kk;
            kk.x = *(uint32_t*)&h0;
            kk.y = *(uint32_t*)&h1;
            *(uint2*)(A0 + OFF_KS + n * ROWB + m * 2) = kk;
        }
    }

    // ---- normalize masses (block_reduce syncs also cover K writes) ----
    float mpv = (t < NN) ? mp[b * NN + t] : 0.0f;
    float mtv = (t < NN) ? mt[b * NN + t] : 0.0f;
    float smp = block_reduce(mpv, red, t);
    float smt = block_reduce(mtv, red, t);
    if (t < NN) {
        a_s[t] = mpv / (smp + EPSD);
        b_s[t] = mtv / (smt + EPSD);
        uh[t]  = __float2half_rn(1.0f);
    }
    __syncthreads();

    // ---- one-time: A-fragments of K^T into registers ----
    // warp w owns output m-rows [w*16, w*16+16); ka[kc*4..+3] = A-frag for
    // (m rows = w*16..+16, k = n in [kc*16,+16)) of K^T, via ldmatrix.trans on K.
    uint32_t ka[64];
    {
        const uint32_t trow = (uint32_t)((lane & 16) ? 8 : 0) + (uint32_t)(lane & 7);
        const uint32_t tcol = (uint32_t)(w * 16 + ((lane & 8) ? 8 : 0)) * 2;
        #pragma unroll
        for (int kc = 0; kc < 16; ++kc) {
            uint32_t addr = ks_base + ((uint32_t)kc * 16 + trow) * ROWB + tcol;
            ldsm_x4_trans(ka[kc * 4], ka[kc * 4 + 1], ka[kc * 4 + 2], ka[kc * 4 + 3], addr);
        }
    }

    const int lm2 = (lane & 3) * 2;   // k-pair base within 16-chunk
    const uint32_t lrowB = ks_base + (uint32_t)(w * 16 + (lane & 15)) * ROWB
                         + ((lane & 16) ? 16u : 0u);
    const int r0 = w * 16 + (lane >> 2);   // output row for epilogues

    // hoist loop-invariant numerators off the per-iter critical path
    const float aa0 = a_s[r0], aa8 = a_s[r0 + 8];
    const float bb0 = b_s[r0], bb8 = b_s[r0 + 8];

    for (int it = 0; it < ITERS; ++it) {
        // ===== Phase A: Ktu[m] = sum_n K^T[m,n]*u[n]; A-frags in regs =====
        float accA[4][4] = {{0,0,0,0},{0,0,0,0},{0,0,0,0},{0,0,0,0}};
        #pragma unroll
        for (int kc = 0; kc < 16; ++kc) {
            uint32_t b0 = *(const uint32_t*)(uh + kc * 16 + lm2);
            uint32_t b1 = *(const uint32_t*)(uh + kc * 16 + lm2 + 8);
            mma16816(accA[kc & 3], ka[kc * 4], ka[kc * 4 + 1],
                     ka[kc * 4 + 2], ka[kc * 4 + 3], b0, b1);
        }
        if ((lane & 3) == 0) {
            float s0 = (accA[0][0] + accA[1][0]) + (accA[2][0] + accA[3][0]);
            float s8 = (accA[0][2] + accA[1][2]) + (accA[2][2] + accA[3][2]);
            float v0 = __fdividef(bb0, s0 + EPSD);
            float v8 = __fdividef(bb8, s8 + EPSD);
            vh[r0]     = __float2half_rn(v0);
            vh[r0 + 8] = __float2half_rn(v8);
            if (it == ITERS - 1) {
                v_s[r0]     = v0;
                v_s[r0 + 8] = v8;
            }
        }
        __syncthreads();

        // ===== Phase B: Kv[n] = sum_m K[n,m]*v[m]; warp w rows [w*16,+16) =====
        float accB[4][4] = {{0,0,0,0},{0,0,0,0},{0,0,0,0},{0,0,0,0}};
        #pragma unroll
        for (int kc = 0; kc < 16; ++kc) {
            uint32_t b0 = *(const uint32_t*)(vh + kc * 16 + lm2);
            uint32_t b1 = *(const uint32_t*)(vh + kc * 16 + lm2 + 8);
            uint32_t A0r, A1r, A2r, A3r;
            ldsm_x4(A0r, A1r, A2r, A3r, lrowB + (uint32_t)kc * 32);
            mma16816(accB[kc & 3], A0r, A1r, A2r, A3r, b0, b1);
        }
        if ((lane & 3) == 0) {
            float s0 = (accB[0][0] + accB[1][0]) + (accB[2][0] + accB[3][0]);
            float s8 = (accB[0][2] + accB[1][2]) + (accB[2][2] + accB[3][2]);
            float u0 = __fdividef(aa0, s0 + EPSD);
            float u8 = __fdividef(aa8, s8 + EPSD);
            uh[r0]     = __float2half_rn(u0);
            uh[r0 + 8] = __float2half_rn(u8);
            if (it == ITERS - 1) {
                u_s[r0]     = u0;
                u_s[r0 + 8] = u8;
            }
        }
        __syncthreads();
    }

    // ===== final cost: sum_nm u[n]*K[n,m]*v[m]*C[n,m] =====
    float csum = 0.0f;
    {
        const float4* C4 = (const float4*)Cb;
        for (int i = t; i < (NN * NN / 4); i += THREADS) {
            float4 c4 = C4[i];
            int n = i >> 6;
            int m = (i & 63) << 2;
            uint2 kk = *(const uint2*)(A0 + OFF_KS + n * ROWB + m * 2);
            float2 f0 = __half22float2(*(__half2*)&kk.x);
            float2 f1 = __half22float2(*(__half2*)&kk.y);
            float4 vv = *(const float4*)(v_s + m);
            float un = u_s[n];
            float e = f0.x * vv.x * c4.x;
            e = fmaf(f0.y * vv.y, c4.y, e);
            e = fmaf(f1.x * vv.z, c4.z, e);
            e = fmaf(f1.y * vv.w, c4.w, e);
            csum = fmaf(un, e, csum);
        }
    }
    float tot = block_reduce(csum, red, t);
    if (t == 0) g_batch_cost[b] = tot;
}

// deterministic final mean over batches
__global__ void sinkhorn_reduce(float* __restrict__ out) {
    __shared__ float sm[256];
    const int t = threadIdx.x;
    float s = 0.0f;
    #pragma unroll
    for (int i = t; i < NB; i += 256) s += g_batch_cost[i];
    sm[t] = s;
    __syncthreads();
    #pragma unroll
    for (int k = 128; k > 0; k >>= 1) {
        if (t < k) sm[t] += sm[t + k];
        __syncthreads();
    }
    if (t == 0) out[0] = sm[0] * (1.0f / (float)NB);
}

// no-op padding so ncu's "-s 5 -c 1" lands on sinkhorn_main (5 launches/call)
__global__ void sinkhorn_pad() {}

extern "C" void kernel_launch(void* const* d_in, const int* in_sizes, int n_in,
                              void* d_out, int out_size) {
    (void)in_sizes; (void)n_in; (void)out_size;
    const float* C  = (const float*)d_in[0];
    const float* mp = (const float*)d_in[1];
    const float* mt = (const float*)d_in[2];
    float* out = (float*)d_out;

    cudaFuncSetAttribute(sinkhorn_main,
                         cudaFuncAttributeMaxDynamicSharedMemorySize, SMEM_BYTES);
    sinkhorn_main<<<NB, THREADS, SMEM_BYTES>>>(C, mp, mt);
    sinkhorn_reduce<<<1, 256>>>(out);
    sinkhorn_pad<<<1, 32>>>();
    sinkhorn_pad<<<1, 32>>>();
    sinkhorn_pad<<<1, 32>>>();
}

// round 9
// speedup vs baseline: 1.0392x; 1.0392x over previous
#include <cuda_runtime.h>
#include <cuda_fp16.h>
#include <cstdint>

#define NB      1024
#define NN      256
#define ITERS   100
#define EPSD    1e-8f
#define THREADS 512

// padded K layout: 256 rows x 264 halves (528 B row stride)
#define ROWB    528

// smem byte offsets
#define OFF_KS   0                 // 256*264*2 = 135168
#define OFF_UH   135168            // 256 half
#define OFF_VH   135680            // 256 half
#define OFF_US   136192            // 256 f32
#define OFF_VS   137216
#define OFF_AS   138240
#define OFF_BS   139264
#define OFF_RED  140288            // 16 f32
#define SMEM_BYTES 140352

__device__ float g_batch_cost[NB];
__device__ unsigned int g_done_count = 0;

__device__ __forceinline__ uint32_t smem_u32(const void* p) {
    uint32_t r;
    asm("{ .reg .u64 t; cvta.to.shared.u64 t, %1; cvt.u32.u64 %0, t; }" : "=r"(r) : "l"(p));
    return r;
}

__device__ __forceinline__ void ldsm_x4(uint32_t& r0, uint32_t& r1, uint32_t& r2,
                                        uint32_t& r3, uint32_t addr) {
    asm volatile("ldmatrix.sync.aligned.m8n8.x4.shared.b16 {%0,%1,%2,%3}, [%4];"
                 : "=r"(r0), "=r"(r1), "=r"(r2), "=r"(r3) : "r"(addr));
}

__device__ __forceinline__ void ldsm_x4_trans(uint32_t& r0, uint32_t& r1, uint32_t& r2,
                                              uint32_t& r3, uint32_t addr) {
    asm volatile("ldmatrix.sync.aligned.m8n8.x4.trans.shared.b16 {%0,%1,%2,%3}, [%4];"
                 : "=r"(r0), "=r"(r1), "=r"(r2), "=r"(r3) : "r"(addr));
}

__device__ __forceinline__ void mma16816(float c[4], uint32_t a0, uint32_t a1,
                                         uint32_t a2, uint32_t a3,
                                         uint32_t b0, uint32_t b1) {
    asm volatile(
        "mma.sync.aligned.m16n8k16.row.col.f32.f16.f16.f32 "
        "{%0,%1,%2,%3}, {%4,%5,%6,%7}, {%8,%9}, {%0,%1,%2,%3};"
        : "+f"(c[0]), "+f"(c[1]), "+f"(c[2]), "+f"(c[3])
        : "r"(a0), "r"(a1), "r"(a2), "r"(a3), "r"(b0), "r"(b1));
}

// exp(-10*c) = 2^(-10*log2e*c), deg-5 poly, rel err ~2.4e-6
__device__ __forceinline__ float fast_exp_n10(float c) {
    float t = c * (-14.426950408889634f);
    float r = rintf(t);
    float f = t - r;
    float p = 1.3333558146e-3f;
    p = fmaf(p, f, 9.6181291076e-3f);
    p = fmaf(p, f, 5.5504108664e-2f);
    p = fmaf(p, f, 2.4022650696e-1f);
    p = fmaf(p, f, 6.9314718056e-1f);
    p = fmaf(p, f, 1.0f);
    return __int_as_float(__float_as_int(p) + (((int)r) << 23));
}

__device__ __forceinline__ float block_reduce(float val, float* red, int t) {
    #pragma unroll
    for (int o = 16; o > 0; o >>= 1)
        val += __shfl_xor_sync(0xffffffffu, val, o);
    if ((t & 31) == 0) red[t >> 5] = val;
    __syncthreads();
    if (t < 32) {
        float v2 = (t < (THREADS / 32)) ? red[t] : 0.0f;
        #pragma unroll
        for (int o = 8; o > 0; o >>= 1)
            v2 += __shfl_xor_sync(0xffffffffu, v2, o);
        if (t == 0) red[0] = v2;
    }
    __syncthreads();
    float out = red[0];
    __syncthreads();
    return out;
}

__global__ void __launch_bounds__(THREADS, 1)
sinkhorn_main(const float* __restrict__ Cmat,
              const float* __restrict__ mp,
              const float* __restrict__ mt,
              float* __restrict__ out) {
    extern __shared__ __align__(16) char A0[];
    __half* uh  = (__half*)(A0 + OFF_UH);
    __half* vh  = (__half*)(A0 + OFF_VH);
    float*  u_s = (float*)(A0 + OFF_US);
    float*  v_s = (float*)(A0 + OFF_VS);
    float*  a_s = (float*)(A0 + OFF_AS);
    float*  b_s = (float*)(A0 + OFF_BS);
    float*  red = (float*)(A0 + OFF_RED);

    const int t    = threadIdx.x;
    const int lane = t & 31;
    const int w    = t >> 5;              // warp 0..15
    const int b    = blockIdx.x;
    const float* Cb = Cmat + (size_t)b * (NN * NN);
    const uint32_t ks_base = smem_u32(A0 + OFF_KS);

    // ---- build K = exp(-C/eps) fp16 into padded row-major smem ----
    {
        const float4* C4 = (const float4*)Cb;
        for (int i = t; i < (NN * NN / 4); i += THREADS) {
            float4 c4 = C4[i];
            int n = i >> 6;
            int m = (i & 63) << 2;
            __half2 h0 = __floats2half2_rn(fast_exp_n10(c4.x), fast_exp_n10(c4.y));
            __half2 h1 = __floats2half2_rn(fast_exp_n10(c4.z), fast_exp_n10(c4.w));
            uint2 kk;
            kk.x = *(uint32_t*)&h0;
            kk.y = *(uint32_t*)&h1;
            *(uint2*)(A0 + OFF_KS + n * ROWB + m * 2) = kk;
        }
    }

    // ---- normalize masses (block_reduce syncs also cover K writes) ----
    float mpv = (t < NN) ? mp[b * NN + t] : 0.0f;
    float mtv = (t < NN) ? mt[b * NN + t] : 0.0f;
    float smp = block_reduce(mpv, red, t);
    float smt = block_reduce(mtv, red, t);
    if (t < NN) {
        a_s[t] = mpv / (smp + EPSD);
        b_s[t] = mtv / (smt + EPSD);
        uh[t]  = __float2half_rn(1.0f);
    }
    __syncthreads();

    // addressing
    const uint32_t trow  = (uint32_t)((lane & 16) ? 8 : 0) + (uint32_t)(lane & 7);
    const uint32_t tcol  = (uint32_t)(w * 16 + ((lane & 8) ? 8 : 0)) * 2;
    const uint32_t addrA = ks_base + trow * ROWB + tcol;          // + kc*16*ROWB
    const uint32_t lrowB = ks_base + (uint32_t)(w * 16 + (lane & 15)) * ROWB
                         + ((lane & 16) ? 16u : 0u);              // + kc*32

    // ---- one-time frag loads: split 50/50 between phases ----
    // Phase A (K^T A-frags) even kc in regs; Phase B (K A-frags) odd kc in regs.
    uint32_t kaE[32];   // 8 chunks x 4
    uint32_t kbO[32];
    #pragma unroll
    for (int j = 0; j < 8; ++j) {
        int kc = 2 * j;
        ldsm_x4_trans(kaE[j * 4], kaE[j * 4 + 1], kaE[j * 4 + 2], kaE[j * 4 + 3],
                      addrA + (uint32_t)kc * (16 * ROWB));
        int kco = 2 * j + 1;
        ldsm_x4(kbO[j * 4], kbO[j * 4 + 1], kbO[j * 4 + 2], kbO[j * 4 + 3],
                lrowB + (uint32_t)kco * 32);
    }

    const int lm2 = (lane & 3) * 2;   // k-pair base within 16-chunk
    const int r0 = w * 16 + (lane >> 2);   // output row for epilogues

    const float aa0 = a_s[r0], aa8 = a_s[r0 + 8];
    const float bb0 = b_s[r0], bb8 = b_s[r0 + 8];

    for (int it = 0; it < ITERS; ++it) {
        // ===== Phase A: Ktu[m] = sum_n K^T[m,n]*u[n] =====
        float accA[4][4] = {{0,0,0,0},{0,0,0,0},{0,0,0,0},{0,0,0,0}};
        #pragma unroll
        for (int j = 0; j < 8; ++j) {
            // even chunk from regs
            {
                int kc = 2 * j;
                uint32_t b0 = *(const uint32_t*)(uh + kc * 16 + lm2);
                uint32_t b1 = *(const uint32_t*)(uh + kc * 16 + lm2 + 8);
                mma16816(accA[kc & 3], kaE[j * 4], kaE[j * 4 + 1],
                         kaE[j * 4 + 2], kaE[j * 4 + 3], b0, b1);
            }
            // odd chunk via ldsm (overlaps tensor with crossbar)
            {
                int kc = 2 * j + 1;
                uint32_t b0 = *(const uint32_t*)(uh + kc * 16 + lm2);
                uint32_t b1 = *(const uint32_t*)(uh + kc * 16 + lm2 + 8);
                uint32_t A0r, A1r, A2r, A3r;
                ldsm_x4_trans(A0r, A1r, A2r, A3r, addrA + (uint32_t)kc * (16 * ROWB));
                mma16816(accA[kc & 3], A0r, A1r, A2r, A3r, b0, b1);
            }
        }
        if ((lane & 3) == 0) {
            float s0 = (accA[0][0] + accA[1][0]) + (accA[2][0] + accA[3][0]);
            float s8 = (accA[0][2] + accA[1][2]) + (accA[2][2] + accA[3][2]);
            float v0 = __fdividef(bb0, s0 + EPSD);
            float v8 = __fdividef(bb8, s8 + EPSD);
            vh[r0]     = __float2half_rn(v0);
            vh[r0 + 8] = __float2half_rn(v8);
            if (it == ITERS - 1) {
                v_s[r0]     = v0;
                v_s[r0 + 8] = v8;
            }
        }
        __syncthreads();

        // ===== Phase B: Kv[n] = sum_m K[n,m]*v[m] =====
        float accB[4][4] = {{0,0,0,0},{0,0,0,0},{0,0,0,0},{0,0,0,0}};
        #pragma unroll
        for (int j = 0; j < 8; ++j) {
            // even chunk via ldsm
            {
                int kc = 2 * j;
                uint32_t b0 = *(const uint32_t*)(vh + kc * 16 + lm2);
                uint32_t b1 = *(const uint32_t*)(vh + kc * 16 + lm2 + 8);
                uint32_t A0r, A1r, A2r, A3r;
                ldsm_x4(A0r, A1r, A2r, A3r, lrowB + (uint32_t)kc * 32);
                mma16816(accB[kc & 3], A0r, A1r, A2r, A3r, b0, b1);
            }
            // odd chunk from regs
            {
                int kc = 2 * j + 1;
                uint32_t b0 = *(const uint32_t*)(vh + kc * 16 + lm2);
                uint32_t b1 = *(const uint32_t*)(vh + kc * 16 + lm2 + 8);
                mma16816(accB[kc & 3], kbO[j * 4], kbO[j * 4 + 1],
                         kbO[j * 4 + 2], kbO[j * 4 + 3], b0, b1);
            }
        }
        if ((lane & 3) == 0) {
            float s0 = (accB[0][0] + accB[1][0]) + (accB[2][0] + accB[3][0]);
            float s8 = (accB[0][2] + accB[1][2]) + (accB[2][2] + accB[3][2]);
            float u0 = __fdividef(aa0, s0 + EPSD);
            float u8 = __fdividef(aa8, s8 + EPSD);
            uh[r0]     = __float2half_rn(u0);
            uh[r0 + 8] = __float2half_rn(u8);
            if (it == ITERS - 1) {
                u_s[r0]     = u0;
                u_s[r0 + 8] = u8;
            }
        }
        __syncthreads();
    }

    // ===== final cost: sum_nm u[n]*K[n,m]*v[m]*C[n,m] =====
    float csum = 0.0f;
    {
        const float4* C4 = (const float4*)Cb;
        for (int i = t; i < (NN * NN / 4); i += THREADS) {
            float4 c4 = C4[i];
            int n = i >> 6;
            int m = (i & 63) << 2;
            uint2 kk = *(const uint2*)(A0 + OFF_KS + n * ROWB + m * 2);
            float2 f0 = __half22float2(*(__half2*)&kk.x);
            float2 f1 = __half22float2(*(__half2*)&kk.y);
            float4 vv = *(const float4*)(v_s + m);
            float un = u_s[n];
            float e = f0.x * vv.x * c4.x;
            e = fmaf(f0.y * vv.y, c4.y, e);
            e = fmaf(f1.x * vv.z, c4.z, e);
            e = fmaf(f1.y * vv.w, c4.w, e);
            csum = fmaf(un, e, csum);
        }
    }
    float tot = block_reduce(csum, red, t);
    if (t == 0) g_batch_cost[b] = tot;

    // ===== last-block fused mean (deterministic fixed-order sum) =====
    __threadfence();
    if (t == 0) {
        unsigned int r = atomicAdd(&g_done_count, 1u);
        red[0] = (r == NB - 1) ? 1.0f : 0.0f;
    }
    __syncthreads();
    if (red[0] != 0.0f) {
        __threadfence();
        float s = 0.0f;
        #pragma unroll
        for (int i = t; i < NB; i += THREADS) s += g_batch_cost[i];
        float gt = block_reduce(s, red, t);
        if (t == 0) {
            out[0] = gt * (1.0f / (float)NB);
            g_done_count = 0;              // reset for next graph replay
        }
    }
}

extern "C" void kernel_launch(void* const* d_in, const int* in_sizes, int n_in,
                              void* d_out, int out_size) {
    (void)in_sizes; (void)n_in; (void)out_size;
    const float* C  = (const float*)d_in[0];
    const float* mp = (const float*)d_in[1];
    const float* mt = (const float*)d_in[2];
    float* out = (float*)d_out;

    cudaFuncSetAttribute(sinkhorn_main,
                         cudaFuncAttributeMaxDynamicSharedMemorySize, SMEM_BYTES);
    sinkhorn_main<<<NB, THREADS, SMEM_BYTES>>>(C, mp, mt, out);
}

// round 11
// speedup vs baseline: 1.1162x; 1.0740x over previous
#include <cuda_runtime.h>
#include <cuda_fp16.h>
#include <cstdint>

#define NB      1024
#define NN      256
#define ITERS   100
#define EPSD    1e-8f
#define THREADS 512

// fp8 K layout: 256 rows x 272 bytes (16B-aligned rows, conflict-free ldsm)
#define ROWK    272

// smem byte offsets
#define OFF_K    0          // K    row-major fp8 (K^ = 16*K)   69632 B
#define OFF_KT   69632      // K^T  row-major fp8               69632 B
#define OFF_UH   139264     // 256 fp8 (u-hat)
#define OFF_VH   139520     // 256 fp8 (v-hat)
#define OFF_US   139776     // 256 f32
#define OFF_VS   140800     // 256 f32
#define OFF_AS   141824     // 256 f32
#define OFF_BS   142848     // 256 f32
#define OFF_RED  143872     // 16 f32
#define SMEM_BYTES 143936

// scaling: K^=16K, u^=64u, v^=512v  ->  numerators x 2^19, eps terms scaled
#define NUM_SCALE 524288.0f
#define EPS_A     1.024e-5f     // 1024 * EPSD  (Phase A denominator = 1024*Ktu)
#define EPS_B     8.192e-5f     // 8192 * EPSD  (Phase B denominator = 8192*Kv)

__device__ float g_batch_cost[NB];
__device__ unsigned int g_done_count = 0;

__device__ __forceinline__ uint32_t smem_u32(const void* p) {
    uint32_t r;
    asm("{ .reg .u64 t; cvta.to.shared.u64 t, %1; cvt.u32.u64 %0, t; }" : "=r"(r) : "l"(p));
    return r;
}

__device__ __forceinline__ void ldsm_x4(uint32_t& r0, uint32_t& r1, uint32_t& r2,
                                        uint32_t& r3, uint32_t addr) {
    asm volatile("ldmatrix.sync.aligned.m8n8.x4.shared.b16 {%0,%1,%2,%3}, [%4];"
                 : "=r"(r0), "=r"(r1), "=r"(r2), "=r"(r3) : "r"(addr));
}

__device__ __forceinline__ void mma_fp8(float c[4], uint32_t a0, uint32_t a1,
                                        uint32_t a2, uint32_t a3,
                                        uint32_t b0, uint32_t b1) {
    asm volatile(
        "mma.sync.aligned.m16n8k32.row.col.f32.e4m3.e4m3.f32 "
        "{%0,%1,%2,%3}, {%4,%5,%6,%7}, {%8,%9}, {%0,%1,%2,%3};"
        : "+f"(c[0]), "+f"(c[1]), "+f"(c[2]), "+f"(c[3])
        : "r"(a0), "r"(a1), "r"(a2), "r"(a3), "r"(b0), "r"(b1));
}

// 16*exp(-10*c) = 2^(-10*log2e*c + 4), deg-5 poly, rel err ~2.4e-6
__device__ __forceinline__ float fast_exp_n10_x16(float c) {
    float t = c * (-14.426950408889634f);
    float r = rintf(t);
    float f = t - r;
    float p = 1.3333558146e-3f;
    p = fmaf(p, f, 9.6181291076e-3f);
    p = fmaf(p, f, 5.5504108664e-2f);
    p = fmaf(p, f, 2.4022650696e-1f);
    p = fmaf(p, f, 6.9314718056e-1f);
    p = fmaf(p, f, 1.0f);
    return __int_as_float(__float_as_int(p) + ((((int)r) + 4) << 23));
}

__device__ __forceinline__ uint32_t pack_e4m3_4(float f0, float f1, float f2, float f3) {
    unsigned short lo, hi;
    asm("cvt.rn.satfinite.e4m3x2.f32 %0, %1, %2;" : "=h"(lo) : "f"(f1), "f"(f0));
    asm("cvt.rn.satfinite.e4m3x2.f32 %0, %1, %2;" : "=h"(hi) : "f"(f3), "f"(f2));
    return (uint32_t)lo | ((uint32_t)hi << 16);
}

__device__ __forceinline__ float2 unpack_e4m3_2(unsigned short v) {
    uint32_t h;
    asm("cvt.rn.f16x2.e4m3x2 %0, %1;" : "=r"(h) : "h"(v));
    __half2 hh = *(__half2*)&h;
    return __half22float2(hh);
}

__device__ __forceinline__ float block_reduce(float val, float* red, int t) {
    #pragma unroll
    for (int o = 16; o > 0; o >>= 1)
        val += __shfl_xor_sync(0xffffffffu, val, o);
    if ((t & 31) == 0) red[t >> 5] = val;
    __syncthreads();
    if (t < 32) {
        float v2 = (t < (THREADS / 32)) ? red[t] : 0.0f;
        #pragma unroll
        for (int o = 8; o > 0; o >>= 1)
            v2 += __shfl_xor_sync(0xffffffffu, v2, o);
        if (t == 0) red[0] = v2;
    }
    __syncthreads();
    float out = red[0];
    __syncthreads();
    return out;
}

__global__ void __launch_bounds__(THREADS, 1)
sinkhorn_main(const float* __restrict__ Cmat,
              const float* __restrict__ mp,
              const float* __restrict__ mt,
              float* __restrict__ out) {
    extern __shared__ __align__(16) char A0[];
    uint8_t* uh8 = (uint8_t*)(A0 + OFF_UH);
    uint8_t* vh8 = (uint8_t*)(A0 + OFF_VH);
    float*   u_s = (float*)(A0 + OFF_US);
    float*   v_s = (float*)(A0 + OFF_VS);
    float*   a_s = (float*)(A0 + OFF_AS);
    float*   b_s = (float*)(A0 + OFF_BS);
    float*   red = (float*)(A0 + OFF_RED);

    const int t    = threadIdx.x;
    const int lane = t & 31;
    const int w    = t >> 5;              // warp 0..15
    const int b    = blockIdx.x;
    const float* Cb = Cmat + (size_t)b * (NN * NN);

    // ---- build K^ = 16*exp(-C/eps) fp8 (row-major) + K^T copy ----
    {
        const float4* C4 = (const float4*)Cb;
        for (int i = t; i < (NN * NN / 4); i += THREADS) {
            float4 c4 = C4[i];
            int n = i >> 6;
            int m = (i & 63) << 2;
            uint32_t kk = pack_e4m3_4(fast_exp_n10_x16(c4.x), fast_exp_n10_x16(c4.y),
                                      fast_exp_n10_x16(c4.z), fast_exp_n10_x16(c4.w));
            *(uint32_t*)(A0 + OFF_K + n * ROWK + m) = kk;
            ((uint8_t*)(A0 + OFF_KT))[(m + 0) * ROWK + n] = (uint8_t)(kk);
            ((uint8_t*)(A0 + OFF_KT))[(m + 1) * ROWK + n] = (uint8_t)(kk >> 8);
            ((uint8_t*)(A0 + OFF_KT))[(m + 2) * ROWK + n] = (uint8_t)(kk >> 16);
            ((uint8_t*)(A0 + OFF_KT))[(m + 3) * ROWK + n] = (uint8_t)(kk >> 24);
        }
    }

    // ---- normalize masses (block_reduce syncs also cover K writes) ----
    float mpv = (t < NN) ? mp[b * NN + t] : 0.0f;
    float mtv = (t < NN) ? mt[b * NN + t] : 0.0f;
    float smp = block_reduce(mpv, red, t);
    float smt = block_reduce(mtv, red, t);
    if (t < NN) {
        a_s[t] = mpv / (smp + EPSD);
        b_s[t] = mtv / (smt + EPSD);
        uh8[t] = 0x68;                     // e4m3(64.0) = u-hat init (u0 = 1)
    }
    __syncthreads();

    // ---- one-time: ALL A-fragments into registers (no ldsm in loop) ----
    // Phase A uses K^T copy (output m-rows), Phase B uses K copy (output n-rows).
    uint32_t kA[32], kB[32];
    {
        const uint32_t fb_t = smem_u32(A0 + OFF_KT)
                            + (uint32_t)(w * 16 + (lane & 15)) * ROWK
                            + ((lane & 16) ? 16u : 0u);
        const uint32_t fb_k = smem_u32(A0 + OFF_K)
                            + (uint32_t)(w * 16 + (lane & 15)) * ROWK
                            + ((lane & 16) ? 16u : 0u);
        #pragma unroll
        for (int kc = 0; kc < 8; ++kc) {
            ldsm_x4(kA[kc * 4], kA[kc * 4 + 1], kA[kc * 4 + 2], kA[kc * 4 + 3],
                    fb_t + (uint32_t)kc * 32);
            ldsm_x4(kB[kc * 4], kB[kc * 4 + 1], kB[kc * 4 + 2], kB[kc * 4 + 3],
                    fb_k + (uint32_t)kc * 32);
        }
    }

    const int lm4 = (lane & 3) * 4;        // k-byte base within 32-chunk
    const int r0 = w * 16 + (lane >> 2);   // output row for epilogues

    // hoisted scaled numerators
    const float aa0 = a_s[r0] * NUM_SCALE, aa8 = a_s[r0 + 8] * NUM_SCALE;
    const float bb0 = b_s[r0] * NUM_SCALE, bb8 = b_s[r0 + 8] * NUM_SCALE;

    for (int it = 0; it < ITERS; ++it) {
        // ===== Phase A: (K^T u)-hat ; all frags in regs, B = u-hat bcast =====
        float accA[4][4] = {{0,0,0,0},{0,0,0,0},{0,0,0,0},{0,0,0,0}};
        #pragma unroll
        for (int kc = 0; kc < 8; ++kc) {
            uint32_t b0 = *(const uint32_t*)(A0 + OFF_UH + kc * 32 + lm4);
            uint32_t b1 = *(const uint32_t*)(A0 + OFF_UH + kc * 32 + lm4 + 16);
            mma_fp8(accA[kc & 3], kA[kc * 4], kA[kc * 4 + 1],
                    kA[kc * 4 + 2], kA[kc * 4 + 3], b0, b1);
        }
        if ((lane & 3) == 0) {
            float s0 = (accA[0][0] + accA[1][0]) + (accA[2][0] + accA[3][0]);
            float s8 = (accA[0][2] + accA[1][2]) + (accA[2][2] + accA[3][2]);
            float v0 = __fdividef(bb0, s0 + EPS_A);   // = v-hat = 512*v
            float v8 = __fdividef(bb8, s8 + EPS_A);
            unsigned short pp;
            asm("cvt.rn.satfinite.e4m3x2.f32 %0, %1, %2;" : "=h"(pp) : "f"(v8), "f"(v0));
            vh8[r0]     = (uint8_t)pp;
            vh8[r0 + 8] = (uint8_t)(pp >> 8);
            if (it == ITERS - 1) {
                v_s[r0]     = v0 * (1.0f / 512.0f);
                v_s[r0 + 8] = v8 * (1.0f / 512.0f);
            }
        }
        __syncthreads();

        // ===== Phase B: (K v)-hat ; all frags in regs, B = v-hat bcast =====
        float accB[4][4] = {{0,0,0,0},{0,0,0,0},{0,0,0,0},{0,0,0,0}};
        #pragma unroll
        for (int kc = 0; kc < 8; ++kc) {
            uint32_t b0 = *(const uint32_t*)(A0 + OFF_VH + kc * 32 + lm4);
            uint32_t b1 = *(const uint32_t*)(A0 + OFF_VH + kc * 32 + lm4 + 16);
            mma_fp8(accB[kc & 3], kB[kc * 4], kB[kc * 4 + 1],
                    kB[kc * 4 + 2], kB[kc * 4 + 3], b0, b1);
        }
        if ((lane & 3) == 0) {
            float s0 = (accB[0][0] + accB[1][0]) + (accB[2][0] + accB[3][0]);
            float s8 = (accB[0][2] + accB[1][2]) + (accB[2][2] + accB[3][2]);
            float u0 = __fdividef(aa0, s0 + EPS_B);   // = u-hat = 64*u
            float u8 = __fdividef(aa8, s8 + EPS_B);
            unsigned short pp;
            asm("cvt.rn.satfinite.e4m3x2.f32 %0, %1, %2;" : "=h"(pp) : "f"(u8), "f"(u0));
            uh8[r0]     = (uint8_t)pp;
            uh8[r0 + 8] = (uint8_t)(pp >> 8);
            if (it == ITERS - 1) {
                u_s[r0]     = u0 * (1.0f / 64.0f);
                u_s[r0 + 8] = u8 * (1.0f / 64.0f);
            }
        }
        __syncthreads();
    }

    // ===== final cost: sum_nm u[n]*(K^/16)[n,m]*v[m]*C[n,m] =====
    float csum = 0.0f;
    {
        const float4* C4 = (const float4*)Cb;
        for (int i = t; i < (NN * NN / 4); i += THREADS) {
            float4 c4 = C4[i];
            int n = i >> 6;
            int m = (i & 63) << 2;
            uint32_t kk = *(const uint32_t*)(A0 + OFF_K + n * ROWK + m);
            float2 f0 = unpack_e4m3_2((unsigned short)kk);
            float2 f1 = unpack_e4m3_2((unsigned short)(kk >> 16));
            float4 vv = *(const float4*)(v_s + m);
            float un = u_s[n];
            float e = f0.x * vv.x * c4.x;
            e = fmaf(f0.y * vv.y, c4.y, e);
            e = fmaf(f1.x * vv.z, c4.z, e);
            e = fmaf(f1.y * vv.w, c4.w, e);
            csum = fmaf(un, e, csum);
        }
    }
    float tot = block_reduce(csum, red, t);
    if (t == 0) g_batch_cost[b] = tot * (1.0f / 16.0f);

    // ===== last-block fused mean (deterministic fixed-order sum) =====
    __threadfence();
    if (t == 0) {
        unsigned int r = atomicAdd(&g_done_count, 1u);
        red[0] = (r == NB - 1) ? 1.0f : 0.0f;
    }
    __syncthreads();
    if (red[0] != 0.0f) {
        __threadfence();
        float s = 0.0f;
        #pragma unroll
        for (int i = t; i < NB; i += THREADS) s += g_batch_cost[i];
        float gt = block_reduce(s, red, t);
        if (t == 0) {
            out[0] = gt * (1.0f / (float)NB);
            g_done_count = 0;              // reset for next graph replay
        }
    }
}

extern "C" void kernel_launch(void* const* d_in, const int* in_sizes, int n_in,
                              void* d_out, int out_size) {
    (void)in_sizes; (void)n_in; (void)out_size;
    const float* C  = (const float*)d_in[0];
    const float* mp = (const float*)d_in[1];
    const float* mt = (const float*)d_in[2];
    float* out = (float*)d_out;

    cudaFuncSetAttribute(sinkhorn_main,
                         cudaFuncAttributeMaxDynamicSharedMemorySize, SMEM_BYTES);
    sinkhorn_main<<<NB, THREADS, SMEM_BYTES>>>(C, mp, mt, out);
}

// round 12
// speedup vs baseline: 1.1187x; 1.0023x over previous
#include <cuda_runtime.h>
#include <cuda_fp16.h>
#include <cstdint>

#define NB      1024
#define NN      256
#define ITERS   100
#define EPSD    1e-8f
#define THREADS 512

// fp8 K layout: 256 rows x 272 bytes (16B-aligned rows, conflict-free ldsm)
#define ROWK    272

// smem byte offsets
#define OFF_K    0          // K    row-major fp8 (K^ = 16*K)   69632 B
#define OFF_KT   69632      // K^T  row-major fp8               69632 B
#define OFF_UH   139264     // 256 fp8 (u-hat)
#define OFF_VH   139520     // 256 fp8 (v-hat)
#define OFF_US   139776     // 256 f32
#define OFF_VS   140800     // 256 f32
#define OFF_AS   141824     // 256 f32
#define OFF_BS   142848     // 256 f32
#define OFF_RED  143872     // 16 f32
#define SMEM_BYTES 143936

// scaling: K^=16K, u^=64u, v^=512v  ->  numerators x 2^19, eps terms scaled
#define NUM_SCALE 524288.0f
#define EPS_A     1.024e-5f     // 1024 * EPSD  (Phase A denominator = 1024*Ktu)
#define EPS_B     8.192e-5f     // 8192 * EPSD  (Phase B denominator = 8192*Kv)

__device__ float g_batch_cost[NB];
__device__ unsigned int g_done_count = 0;

__device__ __forceinline__ uint32_t smem_u32(const void* p) {
    uint32_t r;
    asm("{ .reg .u64 t; cvta.to.shared.u64 t, %1; cvt.u32.u64 %0, t; }" : "=r"(r) : "l"(p));
    return r;
}

__device__ __forceinline__ void ldsm_x4(uint32_t& r0, uint32_t& r1, uint32_t& r2,
                                        uint32_t& r3, uint32_t addr) {
    asm volatile("ldmatrix.sync.aligned.m8n8.x4.shared.b16 {%0,%1,%2,%3}, [%4];"
                 : "=r"(r0), "=r"(r1), "=r"(r2), "=r"(r3) : "r"(addr));
}

__device__ __forceinline__ void mma_fp8(float c[4], uint32_t a0, uint32_t a1,
                                        uint32_t a2, uint32_t a3,
                                        uint32_t b0, uint32_t b1) {
    asm volatile(
        "mma.sync.aligned.m16n8k32.row.col.f32.e4m3.e4m3.f32 "
        "{%0,%1,%2,%3}, {%4,%5,%6,%7}, {%8,%9}, {%0,%1,%2,%3};"
        : "+f"(c[0]), "+f"(c[1]), "+f"(c[2]), "+f"(c[3])
        : "r"(a0), "r"(a1), "r"(a2), "r"(a3), "r"(b0), "r"(b1));
}

// 16*exp(-10*c) = 2^(-10*log2e*c + 4), deg-5 poly, rel err ~2.4e-6
__device__ __forceinline__ float fast_exp_n10_x16(float c) {
    float t = c * (-14.426950408889634f);
    float r = rintf(t);
    float f = t - r;
    float p = 1.3333558146e-3f;
    p = fmaf(p, f, 9.6181291076e-3f);
    p = fmaf(p, f, 5.5504108664e-2f);
    p = fmaf(p, f, 2.4022650696e-1f);
    p = fmaf(p, f, 6.9314718056e-1f);
    p = fmaf(p, f, 1.0f);
    return __int_as_float(__float_as_int(p) + ((((int)r) + 4) << 23));
}

__device__ __forceinline__ uint32_t pack_e4m3_4(float f0, float f1, float f2, float f3) {
    unsigned short lo, hi;
    asm("cvt.rn.satfinite.e4m3x2.f32 %0, %1, %2;" : "=h"(lo) : "f"(f1), "f"(f0));
    asm("cvt.rn.satfinite.e4m3x2.f32 %0, %1, %2;" : "=h"(hi) : "f"(f3), "f"(f2));
    return (uint32_t)lo | ((uint32_t)hi << 16);
}

__device__ __forceinline__ float2 unpack_e4m3_2(unsigned short v) {
    uint32_t h;
    asm("cvt.rn.f16x2.e4m3x2 %0, %1;" : "=r"(h) : "h"(v));
    __half2 hh = *(__half2*)&h;
    return __half22float2(hh);
}

__device__ __forceinline__ float block_reduce(float val, float* red, int t) {
    #pragma unroll
    for (int o = 16; o > 0; o >>= 1)
        val += __shfl_xor_sync(0xffffffffu, val, o);
    if ((t & 31) == 0) red[t >> 5] = val;
    __syncthreads();
    if (t < 32) {
        float v2 = (t < (THREADS / 32)) ? red[t] : 0.0f;
        #pragma unroll
        for (int o = 8; o > 0; o >>= 1)
            v2 += __shfl_xor_sync(0xffffffffu, v2, o);
        if (t == 0) red[0] = v2;
    }
    __syncthreads();
    float out = red[0];
    __syncthreads();
    return out;
}

__global__ void __launch_bounds__(THREADS, 1)
sinkhorn_main(const float* __restrict__ Cmat,
              const float* __restrict__ mp,
              const float* __restrict__ mt,
              float* __restrict__ out) {
    extern __shared__ __align__(16) char A0[];
    uint8_t* uh8 = (uint8_t*)(A0 + OFF_UH);
    uint8_t* vh8 = (uint8_t*)(A0 + OFF_VH);
    float*   u_s = (float*)(A0 + OFF_US);
    float*   v_s = (float*)(A0 + OFF_VS);
    float*   a_s = (float*)(A0 + OFF_AS);
    float*   b_s = (float*)(A0 + OFF_BS);
    float*   red = (float*)(A0 + OFF_RED);

    const int t    = threadIdx.x;
    const int lane = t & 31;
    const int w    = t >> 5;              // warp 0..15
    const int b    = blockIdx.x;
    const float* Cb = Cmat + (size_t)b * (NN * NN);

    // ---- build K^ = 16*exp(-C/eps) fp8 (row-major) + K^T copy ----
    {
        const float4* C4 = (const float4*)Cb;
        for (int i = t; i < (NN * NN / 4); i += THREADS) {
            float4 c4 = C4[i];
            int n = i >> 6;
            int m = (i & 63) << 2;
            uint32_t kk = pack_e4m3_4(fast_exp_n10_x16(c4.x), fast_exp_n10_x16(c4.y),
                                      fast_exp_n10_x16(c4.z), fast_exp_n10_x16(c4.w));
            *(uint32_t*)(A0 + OFF_K + n * ROWK + m) = kk;
            ((uint8_t*)(A0 + OFF_KT))[(m + 0) * ROWK + n] = (uint8_t)(kk);
            ((uint8_t*)(A0 + OFF_KT))[(m + 1) * ROWK + n] = (uint8_t)(kk >> 8);
            ((uint8_t*)(A0 + OFF_KT))[(m + 2) * ROWK + n] = (uint8_t)(kk >> 16);
            ((uint8_t*)(A0 + OFF_KT))[(m + 3) * ROWK + n] = (uint8_t)(kk >> 24);
        }
    }

    // ---- normalize masses (block_reduce syncs also cover K writes) ----
    float mpv = (t < NN) ? mp[b * NN + t] : 0.0f;
    float mtv = (t < NN) ? mt[b * NN + t] : 0.0f;
    float smp = block_reduce(mpv, red, t);
    float smt = block_reduce(mtv, red, t);
    if (t < NN) {
        a_s[t] = mpv / (smp + EPSD);
        b_s[t] = mtv / (smt + EPSD);
        uh8[t] = 0x68;                     // e4m3(64.0) = u-hat init (u0 = 1)
    }
    __syncthreads();

    // ---- one-time: ALL A-fragments into registers (no ldsm in loop) ----
    // Phase A uses K^T copy (output m-rows), Phase B uses K copy (output n-rows).
    uint32_t kA[32], kB[32];
    {
        const uint32_t fb_t = smem_u32(A0 + OFF_KT)
                            + (uint32_t)(w * 16 + (lane & 15)) * ROWK
                            + ((lane & 16) ? 16u : 0u);
        const uint32_t fb_k = smem_u32(A0 + OFF_K)
                            + (uint32_t)(w * 16 + (lane & 15)) * ROWK
                            + ((lane & 16) ? 16u : 0u);
        #pragma unroll
        for (int kc = 0; kc < 8; ++kc) {
            ldsm_x4(kA[kc * 4], kA[kc * 4 + 1], kA[kc * 4 + 2], kA[kc * 4 + 3],
                    fb_t + (uint32_t)kc * 32);
            ldsm_x4(kB[kc * 4], kB[kc * 4 + 1], kB[kc * 4 + 2], kB[kc * 4 + 3],
                    fb_k + (uint32_t)kc * 32);
        }
    }

    const int lm4 = (lane & 3) * 4;        // k-byte base within 32-chunk
    const int r0 = w * 16 + (lane >> 2);   // output row for epilogues

    // hoisted scaled numerators
    const float aa0 = a_s[r0] * NUM_SCALE, aa8 = a_s[r0 + 8] * NUM_SCALE;
    const float bb0 = b_s[r0] * NUM_SCALE, bb8 = b_s[r0 + 8] * NUM_SCALE;

    for (int it = 0; it < ITERS; ++it) {
        // ===== Phase A: (K^T u)-hat ; all frags in regs, B = u-hat bcast =====
        float accA[4][4] = {{0,0,0,0},{0,0,0,0},{0,0,0,0},{0,0,0,0}};
        #pragma unroll
        for (int kc = 0; kc < 8; ++kc) {
            uint32_t b0 = *(const uint32_t*)(A0 + OFF_UH + kc * 32 + lm4);
            uint32_t b1 = *(const uint32_t*)(A0 + OFF_UH + kc * 32 + lm4 + 16);
            mma_fp8(accA[kc & 3], kA[kc * 4], kA[kc * 4 + 1],
                    kA[kc * 4 + 2], kA[kc * 4 + 3], b0, b1);
        }
        if ((lane & 3) == 0) {
            float s0 = (accA[0][0] + accA[1][0]) + (accA[2][0] + accA[3][0]);
            float s8 = (accA[0][2] + accA[1][2]) + (accA[2][2] + accA[3][2]);
            float v0 = __fdividef(bb0, s0 + EPS_A);   // = v-hat = 512*v
            float v8 = __fdividef(bb8, s8 + EPS_A);
            unsigned short pp;
            asm("cvt.rn.satfinite.e4m3x2.f32 %0, %1, %2;" : "=h"(pp) : "f"(v8), "f"(v0));
            vh8[r0]     = (uint8_t)pp;
            vh8[r0 + 8] = (uint8_t)(pp >> 8);
            if (it == ITERS - 1) {
                v_s[r0]     = v0 * (1.0f / 512.0f);
                v_s[r0 + 8] = v8 * (1.0f / 512.0f);
            }
        }
        __syncthreads();

        // ===== Phase B: (K v)-hat ; all frags in regs, B = v-hat bcast =====
        float accB[4][4] = {{0,0,0,0},{0,0,0,0},{0,0,0,0},{0,0,0,0}};
        #pragma unroll
        for (int kc = 0; kc < 8; ++kc) {
            uint32_t b0 = *(const uint32_t*)(A0 + OFF_VH + kc * 32 + lm4);
            uint32_t b1 = *(const uint32_t*)(A0 + OFF_VH + kc * 32 + lm4 + 16);
            mma_fp8(accB[kc & 3], kB[kc * 4], kB[kc * 4 + 1],
                    kB[kc * 4 + 2], kB[kc * 4 + 3], b0, b1);
        }
        if ((lane & 3) == 0) {
            float s0 = (accB[0][0] + accB[1][0]) + (accB[2][0] + accB[3][0]);
            float s8 = (accB[0][2] + accB[1][2]) + (accB[2][2] + accB[3][2]);
            float u0 = __fdividef(aa0, s0 + EPS_B);   // = u-hat = 64*u
            float u8 = __fdividef(aa8, s8 + EPS_B);
            unsigned short pp;
            asm("cvt.rn.satfinite.e4m3x2.f32 %0, %1, %2;" : "=h"(pp) : "f"(u8), "f"(u0));
            uh8[r0]     = (uint8_t)pp;
            uh8[r0 + 8] = (uint8_t)(pp >> 8);
            if (it == ITERS - 1) {
                u_s[r0]     = u0 * (1.0f / 64.0f);
                u_s[r0 + 8] = u8 * (1.0f / 64.0f);
            }
        }
        __syncthreads();
    }

    // ===== final cost: sum_nm u[n]*(K^/16)[n,m]*v[m]*C[n,m] =====
    float csum = 0.0f;
    {
        const float4* C4 = (const float4*)Cb;
        for (int i = t; i < (NN * NN / 4); i += THREADS) {
            float4 c4 = C4[i];
            int n = i >> 6;
            int m = (i & 63) << 2;
            uint32_t kk = *(const uint32_t*)(A0 + OFF_K + n * ROWK + m);
            float2 f0 = unpack_e4m3_2((unsigned short)kk);
            float2 f1 = unpack_e4m3_2((unsigned short)(kk >> 16));
            float4 vv = *(const float4*)(v_s + m);
            float un = u_s[n];
            float e = f0.x * vv.x * c4.x;
            e = fmaf(f0.y * vv.y, c4.y, e);
            e = fmaf(f1.x * vv.z, c4.z, e);
            e = fmaf(f1.y * vv.w, c4.w, e);
            csum = fmaf(un, e, csum);
        }
    }
    float tot = block_reduce(csum, red, t);
    if (t == 0) g_batch_cost[b] = tot * (1.0f / 16.0f);

    // ===== last-block fused mean (deterministic fixed-order sum) =====
    __threadfence();
    if (t == 0) {
        unsigned int r = atomicAdd(&g_done_count, 1u);
        red[0] = (r == NB - 1) ? 1.0f : 0.0f;
    }
    __syncthreads();
    if (red[0] != 0.0f) {
        __threadfence();
        float s = 0.0f;
        #pragma unroll
        for (int i = t; i < NB; i += THREADS) s += g_batch_cost[i];
        float gt = block_reduce(s, red, t);
        if (t == 0) {
            out[0] = gt * (1.0f / (float)NB);
            g_done_count = 0;              // reset for next graph replay
        }
    }
}

extern "C" void kernel_launch(void* const* d_in, const int* in_sizes, int n_in,
                              void* d_out, int out_size) {
    (void)in_sizes; (void)n_in; (void)out_size;
    const float* C  = (const float*)d_in[0];
    const float* mp = (const float*)d_in[1];
    const float* mt = (const float*)d_in[2];
    float* out = (float*)d_out;

    cudaFuncSetAttribute(sinkhorn_main,
                         cudaFuncAttributeMaxDynamicSharedMemorySize, SMEM_BYTES);
    sinkhorn_main<<<NB, THREADS, SMEM_BYTES>>>(C, mp, mt, out);
}